// round 1
// baseline (speedup 1.0000x reference)
#include <cuda_runtime.h>
#include <math.h>

// Problem constants (fixed by the dataset)
#define NN 50000
#define EE 800000
#define GG 64
#define ETOT (EE + NN)

// ---------------- static device scratch (no allocation allowed) ----------------
__device__ float g_XL[NN * 128];
__device__ float g_XR[NN * 128];
__device__ float g_BA[NN * 128];
__device__ float g_BB[NN * 128];
__device__ int   g_rowptr[NN + 1];
__device__ int   g_tmp[NN];       // degree counts, then write cursors
__device__ int   g_col[ETOT];     // CSR (by target) source indices
__device__ float g_cnt[GG];       // per-graph node counts

// ---------------- CSR build ----------------
__global__ void k_init_counts(int* cnt, int n) {
    int i = blockIdx.x * blockDim.x + threadIdx.x;
    if (i < n) cnt[i] = 1;  // self-loop contributes 1
}

__global__ void k_hist(const int* __restrict__ tgt, int* cnt, int e) {
    int i = blockIdx.x * blockDim.x + threadIdx.x;
    if (i < e) atomicAdd(&cnt[tgt[i]], 1);
}

// single-block exclusive scan: rowptr[0]=0, rowptr[i+1]=sum counts[0..i]
__global__ void k_scan(const int* __restrict__ counts, int* __restrict__ rowptr, int n) {
    __shared__ int sh[1024];
    __shared__ int carry;
    int tid = threadIdx.x;
    if (tid == 0) { carry = 0; rowptr[0] = 0; }
    __syncthreads();
    for (int base = 0; base < n; base += 1024) {
        int i = base + tid;
        int v = (i < n) ? counts[i] : 0;
        sh[tid] = v;
        __syncthreads();
        for (int off = 1; off < 1024; off <<= 1) {
            int t = (tid >= off) ? sh[tid - off] : 0;
            __syncthreads();
            sh[tid] += t;
            __syncthreads();
        }
        int incl = sh[tid] + carry;
        if (i < n) rowptr[i + 1] = incl;
        __syncthreads();
        if (tid == 1023) carry = incl;  // chunk total + old carry
        __syncthreads();
    }
}

__global__ void k_copy(const int* __restrict__ a, int* __restrict__ b, int n) {
    int i = blockIdx.x * blockDim.x + threadIdx.x;
    if (i < n) b[i] = a[i];
}

__global__ void k_scatter(const int* __restrict__ src, const int* __restrict__ tgt,
                          int* wcur, int* col, int e, int n) {
    int i = blockIdx.x * blockDim.x + threadIdx.x;
    if (i < e) {
        int d = tgt[i];
        int p = atomicAdd(&wcur[d], 1);
        col[p] = src[i];
    } else if (i < e + n) {
        int v = i - e;                 // self loop
        int p = atomicAdd(&wcur[v], 1);
        col[p] = v;
    }
}

// ---------------- GEMM: Y[n,M] = X[n,128] @ W[128,M], M in {128,64} ----------------
template <int M>
__global__ void k_gemm(const float* __restrict__ X, const float* __restrict__ W,
                       float* __restrict__ Y, int n) {
    extern __shared__ float sm[];
    float* Ws = sm;             // 128*M floats
    float* xs = sm + 128 * M;   // 32*128 floats
    const int tid = threadIdx.x;
    const int row0 = blockIdx.x * 32;

    for (int idx = tid; idx < 128 * M; idx += 256) Ws[idx] = W[idx];
    for (int idx = tid; idx < 32 * 128; idx += 256) {
        int r = idx >> 7, c = idx & 127;
        xs[idx] = (row0 + r < n) ? X[(size_t)(row0 + r) * 128 + c] : 0.f;
    }
    __syncthreads();

    constexpr int CPT4 = M / 32;     // float4s per thread (4 or 2)
    const int r  = tid >> 3;         // 0..31 row within tile
    const int cg = (tid & 7) * CPT4; // float4 column base
    float4 acc[CPT4];
#pragma unroll
    for (int j = 0; j < CPT4; j++) acc[j] = make_float4(0.f, 0.f, 0.f, 0.f);
    const float4* Ws4 = (const float4*)Ws;

#pragma unroll 4
    for (int k = 0; k < 128; k++) {
        float a = xs[r * 128 + k];
#pragma unroll
        for (int j = 0; j < CPT4; j++) {
            float4 w = Ws4[k * (M / 4) + cg + j];
            acc[j].x = fmaf(a, w.x, acc[j].x);
            acc[j].y = fmaf(a, w.y, acc[j].y);
            acc[j].z = fmaf(a, w.z, acc[j].z);
            acc[j].w = fmaf(a, w.w, acc[j].w);
        }
    }
    if (row0 + r < n) {
        float4* Y4 = (float4*)(Y + (size_t)(row0 + r) * M);
#pragma unroll
        for (int j = 0; j < CPT4; j++) Y4[cg + j] = acc[j];
    }
}

// ---------------- GATv2 aggregation: warp per node, online softmax ----------------
// HC = heads*channels (feature width), H = heads. V = HC/32 floats per lane.
template <int HC, int H>
__global__ void k_gat(const float* __restrict__ XL, const float* __restrict__ XR,
                      const int* __restrict__ rowptr, const int* __restrict__ col,
                      const float* __restrict__ att, const float* __restrict__ bias,
                      float* __restrict__ Y, int n) {
    constexpr int V  = HC / 32;  // 4 or 2
    constexpr int GW = 32 / H;   // lanes per head group (8 or 32)
    const int lane = threadIdx.x & 31;
    const int node = blockIdx.x * (blockDim.x >> 5) + (threadIdx.x >> 5);
    if (node >= n) return;

    float attv[V], bv[V], xr[V], acc[V];
#pragma unroll
    for (int v = 0; v < V; v++) {
        attv[v] = att[lane * V + v];
        bv[v]   = bias[lane * V + v];
        acc[v]  = 0.f;
    }
    // load xr (target transform) once
    {
        const float* p = XR + (size_t)node * HC + lane * V;
        if (V == 4) {
            float4 t = *(const float4*)p;
            xr[0] = t.x; xr[1] = t.y; xr[2] = t.z; xr[3] = t.w;
        } else {
            float2 t = *(const float2*)p;
            xr[0] = t.x; xr[1] = t.y;
        }
    }

    float m = -3.0e38f, den = 0.f;
    const int e1 = rowptr[node + 1];
    for (int e = rowptr[node]; e < e1; e++) {
        int s = col[e];
        float xl[V];
        const float* p = XL + (size_t)s * HC + lane * V;
        if (V == 4) {
            float4 t = *(const float4*)p;
            xl[0] = t.x; xl[1] = t.y; xl[2] = t.z; xl[3] = t.w;
        } else {
            float2 t = *(const float2*)p;
            xl[0] = t.x; xl[1] = t.y;
        }
        float pscore = 0.f;
#pragma unroll
        for (int v = 0; v < V; v++) {
            float t = xl[v] + xr[v];
            t = (t > 0.f) ? t : 0.2f * t;  // leaky relu
            pscore = fmaf(attv[v], t, pscore);
        }
#pragma unroll
        for (int off = GW >> 1; off > 0; off >>= 1)
            pscore += __shfl_xor_sync(0xffffffffu, pscore, off);

        // online softmax update (per head, replicated across the head's lanes)
        float mn   = fmaxf(m, pscore);
        float corr = __expf(m - mn);
        float w    = __expf(pscore - mn);
        den = den * corr + w;
#pragma unroll
        for (int v = 0; v < V; v++) acc[v] = fmaf(acc[v], corr, w * xl[v]);
        m = mn;
    }

    float inv = 1.f / den;  // every node has a self-loop -> den > 0
    float* yp = Y + (size_t)node * HC + lane * V;
#pragma unroll
    for (int v = 0; v < V; v++) {
        float y = fmaf(acc[v], inv, bv[v]);
        yp[v] = (y > 0.f) ? y : 0.2f * y;  // inter-layer leaky relu
    }
}

// ---------------- global mean pool ----------------
__global__ void k_zero_pool(float* out, float* cnt) {
    int i = blockIdx.x * blockDim.x + threadIdx.x;
    if (i < GG * 64) out[i] = 0.f;
    if (i < GG) cnt[i] = 0.f;
}

__global__ void k_pool(const float* __restrict__ X, const int* __restrict__ batch,
                       float* out, float* cnt, int n) {
    int t = blockIdx.x * blockDim.x + threadIdx.x;
    if (t >= n * 64) return;
    int node = t >> 6, f = t & 63;
    int g = batch[node];
    atomicAdd(&out[g * 64 + f], X[(size_t)node * 64 + f]);
    if (f == 0) atomicAdd(&cnt[g], 1.f);
}

__global__ void k_fin(float* out, const float* __restrict__ cnt) {
    int i = blockIdx.x * blockDim.x + threadIdx.x;
    if (i < GG * 64) out[i] /= fmaxf(cnt[i >> 6], 1.f);
}

// ---------------- launch ----------------
extern "C" void kernel_launch(void* const* d_in, const int* in_sizes, int n_in,
                              void* d_out, int out_size) {
    const float* x     = (const float*)d_in[0];
    const int*   ei    = (const int*)d_in[1];
    const int*   batch = (const int*)d_in[2];
    const float* Wl0 = (const float*)d_in[3];
    const float* Wr0 = (const float*)d_in[4];
    const float* at0 = (const float*)d_in[5];
    const float* b0  = (const float*)d_in[6];
    const float* Wl1 = (const float*)d_in[7];
    const float* Wr1 = (const float*)d_in[8];
    const float* at1 = (const float*)d_in[9];
    const float* b1  = (const float*)d_in[10];
    const float* Wl2 = (const float*)d_in[11];
    const float* Wr2 = (const float*)d_in[12];
    const float* at2 = (const float*)d_in[13];
    const float* b2  = (const float*)d_in[14];
    float* out = (float*)d_out;

    const int n = in_sizes[2];      // 50000
    const int e = in_sizes[1] / 2;  // 800000
    const int* src = ei;
    const int* tgt = ei + e;

    float *pXL, *pXR, *pBA, *pBB, *pcnt;
    int *prow, *ptmp, *pcol;
    cudaGetSymbolAddress((void**)&pXL, g_XL);
    cudaGetSymbolAddress((void**)&pXR, g_XR);
    cudaGetSymbolAddress((void**)&pBA, g_BA);
    cudaGetSymbolAddress((void**)&pBB, g_BB);
    cudaGetSymbolAddress((void**)&prow, g_rowptr);
    cudaGetSymbolAddress((void**)&ptmp, g_tmp);
    cudaGetSymbolAddress((void**)&pcol, g_col);
    cudaGetSymbolAddress((void**)&pcnt, g_cnt);

    const int smem128 = (128 * 128 + 32 * 128) * (int)sizeof(float); // 80 KB
    const int smem64  = (128 * 64  + 32 * 128) * (int)sizeof(float); // 48 KB
    cudaFuncSetAttribute(k_gemm<128>, cudaFuncAttributeMaxDynamicSharedMemorySize, smem128);
    cudaFuncSetAttribute(k_gemm<64>,  cudaFuncAttributeMaxDynamicSharedMemorySize, smem64);

    // --- build CSR by target (shared across layers) ---
    k_init_counts<<<(n + 255) / 256, 256>>>(ptmp, n);
    k_hist<<<(e + 255) / 256, 256>>>(tgt, ptmp, e);
    k_scan<<<1, 1024>>>(ptmp, prow, n);
    k_copy<<<(n + 255) / 256, 256>>>(prow, ptmp, n);
    k_scatter<<<(e + n + 255) / 256, 256>>>(src, tgt, ptmp, pcol, e, n);

    const int gblocks = (n + 31) / 32;
    const int ablocks = (n + 7) / 8;

    // --- layer 0: 128 -> 4x32 concat ---
    k_gemm<128><<<gblocks, 256, smem128>>>(x, Wl0, pXL, n);
    k_gemm<128><<<gblocks, 256, smem128>>>(x, Wr0, pXR, n);
    k_gat<128, 4><<<ablocks, 256>>>(pXL, pXR, prow, pcol, at0, b0, pBA, n);

    // --- layer 1: 128 -> 4x32 concat ---
    k_gemm<128><<<gblocks, 256, smem128>>>(pBA, Wl1, pXL, n);
    k_gemm<128><<<gblocks, 256, smem128>>>(pBA, Wr1, pXR, n);
    k_gat<128, 4><<<ablocks, 256>>>(pXL, pXR, prow, pcol, at1, b1, pBB, n);

    // --- layer 2: 128 -> 1x64 (mean over 1 head = identity) ---
    k_gemm<64><<<gblocks, 256, smem64>>>(pBB, Wl2, pXL, n);
    k_gemm<64><<<gblocks, 256, smem64>>>(pBB, Wr2, pXR, n);
    k_gat<64, 1><<<ablocks, 256>>>(pXL, pXR, prow, pcol, at2, b2, pBA, n);

    // --- global mean pool ---
    k_zero_pool<<<(GG * 64 + 255) / 256, 256>>>(out, pcnt);
    k_pool<<<(n * 64 + 255) / 256, 256>>>(pBA, batch, out, pcnt, n);
    k_fin<<<(GG * 64 + 255) / 256, 256>>>(out, pcnt);
}

// round 2
// speedup vs baseline: 4.0558x; 4.0558x over previous
#include <cuda_runtime.h>
#include <math.h>

#define NN 50000
#define EE 800000
#define GG 64
#define ETOT (EE + NN)

typedef unsigned long long ull;

// ---------------- static device scratch ----------------
__device__ float g_XL[NN * 128];
__device__ float g_XR[NN * 128];
__device__ float g_BA[NN * 128];
__device__ float g_BB[NN * 128];
__device__ int   g_rowptr[NN + 1];
__device__ int   g_tmp[NN];       // counts, then write cursors
__device__ int   g_col[ETOT];     // CSR (by target) source indices
__device__ float g_cnt[GG];

// ---------------- f32x2 helpers ----------------
__device__ __forceinline__ void fma2(ull& d, ull a, ull b) {
    asm("fma.rn.f32x2 %0, %1, %2, %0;" : "+l"(d) : "l"(a), "l"(b));
}

// ---------------- CSR build ----------------
__global__ void k_init_counts(int* cnt, int n) {
    int i = blockIdx.x * blockDim.x + threadIdx.x;
    if (i < n) cnt[i] = 1;  // self-loop
}

__global__ void k_hist(const int* __restrict__ tgt, int* cnt, int e) {
    int i = blockIdx.x * blockDim.x + threadIdx.x;
    if (i < e) atomicAdd(&cnt[tgt[i]], 1);
}

// warp-shuffle scan, single block; writes rowptr[i+1]=incl and cursor[i]=excl
__global__ void k_scan(const int* __restrict__ counts, int* __restrict__ rowptr,
                       int* __restrict__ cursor, int n) {
    __shared__ int wsum[32];
    __shared__ int carry_sh;
    const int tid = threadIdx.x, lane = tid & 31, wid = tid >> 5;
    if (tid == 0) { carry_sh = 0; rowptr[0] = 0; }
    __syncthreads();
    for (int base = 0; base < n; base += 1024) {
        int i = base + tid;
        int v = (i < n) ? counts[i] : 0;
        int incl = v;
#pragma unroll
        for (int off = 1; off < 32; off <<= 1) {
            int t = __shfl_up_sync(0xffffffffu, incl, off);
            if (lane >= off) incl += t;
        }
        if (lane == 31) wsum[wid] = incl;
        __syncthreads();
        if (wid == 0) {
            int w = wsum[lane];
            int wincl = w;
#pragma unroll
            for (int off = 1; off < 32; off <<= 1) {
                int t = __shfl_up_sync(0xffffffffu, wincl, off);
                if (lane >= off) wincl += t;
            }
            wsum[lane] = wincl - w;  // exclusive warp offset
        }
        __syncthreads();
        int excl = carry_sh + wsum[wid] + incl - v;
        if (i < n) { rowptr[i + 1] = excl + v; cursor[i] = excl; }
        __syncthreads();
        if (tid == 1023) carry_sh = excl + v;
        __syncthreads();
    }
}

__global__ void k_scatter(const int* __restrict__ src, const int* __restrict__ tgt,
                          int* wcur, int* col, int e, int n) {
    int i = blockIdx.x * blockDim.x + threadIdx.x;
    if (i < e) {
        int d = tgt[i];
        int p = atomicAdd(&wcur[d], 1);
        col[p] = src[i];
    } else if (i < e + n) {
        int v = i - e;  // self loop
        int p = atomicAdd(&wcur[v], 1);
        col[p] = v;
    }
}

// ---------------- fused dual GEMM (f32x2): XL = X@Wl, XR = X@Wr ----------------
// X[n,128], Wl/Wr[128,M]. Block tile: 64 rows x 128 cols of [Wl|Wr].
// grid.y = 2M/128 chunks. 256 threads; each thread: 8 rows x 4 cols.
// smem: xs duplicated-x 64x128 float2 (64KB) + Ws 64x128 float (32KB, K in 2 stages)
template <int M>
__global__ void k_gemm2(const float* __restrict__ X,
                        const float* __restrict__ Wl, const float* __restrict__ Wr,
                        float* __restrict__ XL, float* __restrict__ XR, int n) {
    extern __shared__ char smraw[];
    float2* xs = (float2*)smraw;                     // [64][128] dup x
    float*  Ws = (float*)(smraw + 64 * 128 * 8);     // [64][128] W chunk (k-stage)
    const int tid = threadIdx.x;
    const int row0 = blockIdx.x * 64;
    const int colbase = blockIdx.y * 128;            // within [0, 2M)

    // fill xs (all 128 k), duplicated
    for (int i = tid; i < 64 * 128; i += 256) {
        int r = i >> 7, c = i & 127;
        float v = (row0 + r < n) ? X[(size_t)(row0 + r) * 128 + c] : 0.f;
        xs[r * 128 + c] = make_float2(v, v);
    }

    const int lane = tid & 31;          // col group: 4 cols at lane*4
    const int wrow = (tid >> 5) * 8;    // 8 rows per thread
    ull acc[16];
#pragma unroll
    for (int i = 0; i < 16; i++) acc[i] = 0ull;

    const ulonglong2* Ws2 = (const ulonglong2*)Ws;

    for (int ks = 0; ks < 128; ks += 64) {
        __syncthreads();
        // fill Ws rows ks..ks+63 (float4 granularity)
        for (int i4 = tid; i4 < 64 * 128 / 4; i4 += 256) {
            int k = i4 >> 5, c4 = i4 & 31;
            int gc = colbase + c4 * 4;
            const float* srcp = (gc < M) ? (Wl + (size_t)(ks + k) * M + gc)
                                         : (Wr + (size_t)(ks + k) * M + gc - M);
            *(float4*)&Ws[k * 128 + c4 * 4] = *(const float4*)srcp;
        }
        __syncthreads();
#pragma unroll 4
        for (int k = 0; k < 64; k++) {
            ulonglong2 w = Ws2[k * 32 + lane];
#pragma unroll
            for (int r = 0; r < 8; r++) {
                ull xd = *(const ull*)&xs[(wrow + r) * 128 + ks + k];
                fma2(acc[r * 2 + 0], xd, w.x);
                fma2(acc[r * 2 + 1], xd, w.y);
            }
        }
    }

    // store
    int c = colbase + lane * 4;
    float* OUT; int cc;
    if (c < M) { OUT = XL; cc = c; } else { OUT = XR; cc = c - M; }
#pragma unroll
    for (int r = 0; r < 8; r++) {
        int row = row0 + wrow + r;
        if (row < n) {
            union { ull u[2]; float4 f; } t;
            t.u[0] = acc[r * 2];
            t.u[1] = acc[r * 2 + 1];
            *(float4*)&OUT[(size_t)row * M + cc] = t.f;
        }
    }
}

// ---------------- GATv2 aggregation: warp per node, online softmax ----------------
template <int HC, int H>
__global__ void k_gat(const float* __restrict__ XL, const float* __restrict__ XR,
                      const int* __restrict__ rowptr, const int* __restrict__ col,
                      const float* __restrict__ att, const float* __restrict__ bias,
                      float* __restrict__ Y, int n) {
    constexpr int V  = HC / 32;
    constexpr int GW = 32 / H;
    const int lane = threadIdx.x & 31;
    const int node = blockIdx.x * (blockDim.x >> 5) + (threadIdx.x >> 5);
    if (node >= n) return;

    float attv[V], bv[V], xr[V], acc[V];
#pragma unroll
    for (int v = 0; v < V; v++) {
        attv[v] = att[lane * V + v];
        bv[v]   = bias[lane * V + v];
        acc[v]  = 0.f;
    }
    {
        const float* p = XR + (size_t)node * HC + lane * V;
        if (V == 4) { float4 t = *(const float4*)p; xr[0]=t.x; xr[1]=t.y; xr[2]=t.z; xr[3]=t.w; }
        else        { float2 t = *(const float2*)p; xr[0]=t.x; xr[1]=t.y; }
    }

    const int e0 = rowptr[node], e1 = rowptr[node + 1];
    float nb[V];
    {
        int s = __ldg(&col[e0]);
        const float* p = XL + (size_t)s * HC + lane * V;
        if (V == 4) { float4 t = *(const float4*)p; nb[0]=t.x; nb[1]=t.y; nb[2]=t.z; nb[3]=t.w; }
        else        { float2 t = *(const float2*)p; nb[0]=t.x; nb[1]=t.y; }
    }

    float m = -3.0e38f, den = 0.f;
    for (int e = e0; e < e1; e++) {
        float xl[V];
#pragma unroll
        for (int v = 0; v < V; v++) xl[v] = nb[v];
        if (e + 1 < e1) {  // prefetch next edge's source row
            int s2 = __ldg(&col[e + 1]);
            const float* p = XL + (size_t)s2 * HC + lane * V;
            if (V == 4) { float4 t = *(const float4*)p; nb[0]=t.x; nb[1]=t.y; nb[2]=t.z; nb[3]=t.w; }
            else        { float2 t = *(const float2*)p; nb[0]=t.x; nb[1]=t.y; }
        }
        float pscore = 0.f;
#pragma unroll
        for (int v = 0; v < V; v++) {
            float t = xl[v] + xr[v];
            t = (t > 0.f) ? t : 0.2f * t;
            pscore = fmaf(attv[v], t, pscore);
        }
#pragma unroll
        for (int off = GW >> 1; off > 0; off >>= 1)
            pscore += __shfl_xor_sync(0xffffffffu, pscore, off);

        float mn   = fmaxf(m, pscore);
        float corr = __expf(m - mn);
        float w    = __expf(pscore - mn);
        den = den * corr + w;
#pragma unroll
        for (int v = 0; v < V; v++) acc[v] = fmaf(acc[v], corr, w * xl[v]);
        m = mn;
    }

    float inv = 1.f / den;
    float* yp = Y + (size_t)node * HC + lane * V;
#pragma unroll
    for (int v = 0; v < V; v++) {
        float y = fmaf(acc[v], inv, bv[v]);
        yp[v] = (y > 0.f) ? y : 0.2f * y;
    }
}

// ---------------- global mean pool ----------------
__global__ void k_zero_pool(float* out, float* cnt) {
    int i = blockIdx.x * blockDim.x + threadIdx.x;
    if (i < GG * 64) out[i] = 0.f;
    if (i < GG) cnt[i] = 0.f;
}

__global__ void k_pool(const float* __restrict__ X, const int* __restrict__ batch,
                       float* out, float* cnt, int n) {
    int t = blockIdx.x * blockDim.x + threadIdx.x;
    if (t >= n * 64) return;
    int node = t >> 6, f = t & 63;
    int g = batch[node];
    atomicAdd(&out[g * 64 + f], X[(size_t)node * 64 + f]);
    if (f == 0) atomicAdd(&cnt[g], 1.f);
}

__global__ void k_fin(float* out, const float* __restrict__ cnt) {
    int i = blockIdx.x * blockDim.x + threadIdx.x;
    if (i < GG * 64) out[i] /= fmaxf(cnt[i >> 6], 1.f);
}

// ---------------- launch ----------------
extern "C" void kernel_launch(void* const* d_in, const int* in_sizes, int n_in,
                              void* d_out, int out_size) {
    const float* x     = (const float*)d_in[0];
    const int*   ei    = (const int*)d_in[1];
    const int*   batch = (const int*)d_in[2];
    const float* Wl0 = (const float*)d_in[3];
    const float* Wr0 = (const float*)d_in[4];
    const float* at0 = (const float*)d_in[5];
    const float* b0  = (const float*)d_in[6];
    const float* Wl1 = (const float*)d_in[7];
    const float* Wr1 = (const float*)d_in[8];
    const float* at1 = (const float*)d_in[9];
    const float* b1  = (const float*)d_in[10];
    const float* Wl2 = (const float*)d_in[11];
    const float* Wr2 = (const float*)d_in[12];
    const float* at2 = (const float*)d_in[13];
    const float* b2  = (const float*)d_in[14];
    float* out = (float*)d_out;

    const int n = in_sizes[2];
    const int e = in_sizes[1] / 2;
    const int* src = ei;
    const int* tgt = ei + e;

    float *pXL, *pXR, *pBA, *pBB, *pcnt;
    int *prow, *ptmp, *pcol;
    cudaGetSymbolAddress((void**)&pXL, g_XL);
    cudaGetSymbolAddress((void**)&pXR, g_XR);
    cudaGetSymbolAddress((void**)&pBA, g_BA);
    cudaGetSymbolAddress((void**)&pBB, g_BB);
    cudaGetSymbolAddress((void**)&prow, g_rowptr);
    cudaGetSymbolAddress((void**)&ptmp, g_tmp);
    cudaGetSymbolAddress((void**)&pcol, g_col);
    cudaGetSymbolAddress((void**)&pcnt, g_cnt);

    const int smem = 64 * 128 * 8 + 64 * 128 * 4;  // 96 KB
    cudaFuncSetAttribute(k_gemm2<128>, cudaFuncAttributeMaxDynamicSharedMemorySize, smem);
    cudaFuncSetAttribute(k_gemm2<64>,  cudaFuncAttributeMaxDynamicSharedMemorySize, smem);

    const int grows = (n + 63) / 64;
    const int ablocks = (n + 7) / 8;

    // layer-0 fused GEMM first (independent of CSR) so ncu capture hits real work
    k_gemm2<128><<<dim3(grows, 2), 256, smem>>>(x, Wl0, Wr0, pXL, pXR, n);

    // --- CSR build (shared across layers) ---
    k_init_counts<<<(n + 255) / 256, 256>>>(ptmp, n);
    k_hist<<<(e + 255) / 256, 256>>>(tgt, ptmp, e);
    k_scan<<<1, 1024>>>(ptmp, prow, ptmp, n);
    k_scatter<<<(e + n + 255) / 256, 256>>>(src, tgt, ptmp, pcol, e, n);

    // --- layer 0 aggregate ---
    k_gat<128, 4><<<ablocks, 256>>>(pXL, pXR, prow, pcol, at0, b0, pBA, n);

    // --- layer 1 ---
    k_gemm2<128><<<dim3(grows, 2), 256, smem>>>(pBA, Wl1, Wr1, pXL, pXR, n);
    k_gat<128, 4><<<ablocks, 256>>>(pXL, pXR, prow, pcol, at1, b1, pBB, n);

    // --- layer 2 (1 head x 64) ---
    k_gemm2<64><<<dim3(grows, 1), 256, smem>>>(pBB, Wl2, Wr2, pXL, pXR, n);
    k_gat<64, 1><<<ablocks, 256>>>(pXL, pXR, prow, pcol, at2, b2, pBA, n);

    // --- global mean pool ---
    k_zero_pool<<<(GG * 64 + 255) / 256, 256>>>(out, pcnt);
    k_pool<<<(n * 64 + 255) / 256, 256>>>(pBA, batch, out, pcnt, n);
    k_fin<<<(GG * 64 + 255) / 256, 256>>>(out, pcnt);
}

// round 3
// speedup vs baseline: 4.4098x; 1.0873x over previous
#include <cuda_runtime.h>
#include <math.h>

#define NN 50000
#define EE 800000
#define GG 64
#define ETOT (EE + NN)
#define SCHUNK 512

typedef unsigned long long ull;

// ---------------- static device scratch ----------------
__device__ float g_XL[NN * 128];
__device__ float g_XR[NN * 128];
__device__ float g_BA[NN * 128];
__device__ float g_BB[NN * 128];
__device__ int   g_rowptr[NN + 1];
__device__ int   g_tmp[NN];        // counts, then write cursors
__device__ int   g_lscan[NN];      // per-element local inclusive scan
__device__ int   g_bsum[256];      // per-block sums -> exclusive offsets
__device__ int   g_col[ETOT];
__device__ float g_cnt[GG];

__device__ __forceinline__ void fma2(ull& d, ull a, ull b) {
    asm("fma.rn.f32x2 %0, %1, %2, %0;" : "+l"(d) : "l"(a), "l"(b));
}

// ---------------- CSR build ----------------
__global__ void k_init_counts(int* cnt, int n) {
    int i = blockIdx.x * blockDim.x + threadIdx.x;
    if (i < n) cnt[i] = 1;  // self-loop
}

__global__ void k_hist(const int* __restrict__ tgt, int* cnt, int e) {
    int i = blockIdx.x * blockDim.x + threadIdx.x;
    if (i < e) atomicAdd(&cnt[tgt[i]], 1);
}

// phase A: per-block (512 elems) inclusive scan + block totals
__global__ void k_scanA(const int* __restrict__ counts, int* __restrict__ lscan,
                        int* __restrict__ bsum, int n) {
    __shared__ int wsum[16];
    const int tid = threadIdx.x, lane = tid & 31, wid = tid >> 5;
    const int i = blockIdx.x * SCHUNK + tid;
    int v = (i < n) ? counts[i] : 0;
    int incl = v;
#pragma unroll
    for (int off = 1; off < 32; off <<= 1) {
        int t = __shfl_up_sync(0xffffffffu, incl, off);
        if (lane >= off) incl += t;
    }
    if (lane == 31) wsum[wid] = incl;
    __syncthreads();
    if (tid < 16) {
        int w = wsum[tid];
        int s = w;
#pragma unroll
        for (int off = 1; off < 16; off <<= 1) {
            int t = __shfl_up_sync(0xffffu, s, off);
            if (tid >= off) s += t;
        }
        wsum[tid] = s - w;  // exclusive warp offset
    }
    __syncthreads();
    incl += wsum[wid];
    if (i < n) lscan[i] = incl;
    if (tid == SCHUNK - 1) bsum[blockIdx.x] = incl;  // block total
}

// phase B: exclusive scan of block sums (nb <= 128) in one block
__global__ void k_scanB(int* bsum, int nb) {
    __shared__ int wsum[4];
    const int tid = threadIdx.x, lane = tid & 31, wid = tid >> 5;
    int v = (tid < nb) ? bsum[tid] : 0;
    int incl = v;
#pragma unroll
    for (int off = 1; off < 32; off <<= 1) {
        int t = __shfl_up_sync(0xffffffffu, incl, off);
        if (lane >= off) incl += t;
    }
    if (lane == 31) wsum[wid] = incl;
    __syncthreads();
    int base = 0;
    for (int w = 0; w < wid; w++) base += wsum[w];
    if (tid < nb) bsum[tid] = base + incl - v;  // exclusive
}

// phase C: fixup -> rowptr (inclusive shifted) + cursor (exclusive)
__global__ void k_scanC(int* __restrict__ counts_cursor, const int* __restrict__ lscan,
                        const int* __restrict__ bsum, int* __restrict__ rowptr, int n) {
    int i = blockIdx.x * blockDim.x + threadIdx.x;
    if (i < n) {
        int c = counts_cursor[i];
        int incl = bsum[i / SCHUNK] + lscan[i];
        rowptr[i + 1] = incl;
        counts_cursor[i] = incl - c;  // write cursor in place
    }
    if (i == 0) rowptr[0] = 0;
}

__global__ void k_scatter(const int* __restrict__ src, const int* __restrict__ tgt,
                          int* wcur, int* col, int e, int n) {
    int i = blockIdx.x * blockDim.x + threadIdx.x;
    if (i < e) {
        int d = tgt[i];
        int p = atomicAdd(&wcur[d], 1);
        col[p] = src[i];
    } else if (i < e + n) {
        int v = i - e;
        int p = atomicAdd(&wcur[v], 1);
        col[p] = v;
    }
}

// ---------------- fused dual GEMM (f32x2): XL = X@Wl, XR = X@Wr ----------------
template <int M>
__global__ void k_gemm2(const float* __restrict__ X,
                        const float* __restrict__ Wl, const float* __restrict__ Wr,
                        float* __restrict__ XL, float* __restrict__ XR, int n) {
    extern __shared__ char smraw[];
    float2* xs = (float2*)smraw;                     // [64][128] dup x
    float*  Ws = (float*)(smraw + 64 * 128 * 8);     // [64][128] W chunk
    const int tid = threadIdx.x;
    const int row0 = blockIdx.x * 64;
    const int colbase = blockIdx.y * 128;

    for (int i = tid; i < 64 * 128; i += 256) {
        int r = i >> 7, c = i & 127;
        float v = (row0 + r < n) ? X[(size_t)(row0 + r) * 128 + c] : 0.f;
        xs[r * 128 + c] = make_float2(v, v);
    }

    const int lane = tid & 31;
    const int wrow = (tid >> 5) * 8;
    ull acc[16];
#pragma unroll
    for (int i = 0; i < 16; i++) acc[i] = 0ull;
    const ulonglong2* Ws2 = (const ulonglong2*)Ws;

    for (int ks = 0; ks < 128; ks += 64) {
        __syncthreads();
        for (int i4 = tid; i4 < 64 * 128 / 4; i4 += 256) {
            int k = i4 >> 5, c4 = i4 & 31;
            int gc = colbase + c4 * 4;
            const float* srcp = (gc < M) ? (Wl + (size_t)(ks + k) * M + gc)
                                         : (Wr + (size_t)(ks + k) * M + gc - M);
            *(float4*)&Ws[k * 128 + c4 * 4] = *(const float4*)srcp;
        }
        __syncthreads();
#pragma unroll 4
        for (int k = 0; k < 64; k++) {
            ulonglong2 w = Ws2[k * 32 + lane];
#pragma unroll
            for (int r = 0; r < 8; r++) {
                ull xd = *(const ull*)&xs[(wrow + r) * 128 + ks + k];
                fma2(acc[r * 2 + 0], xd, w.x);
                fma2(acc[r * 2 + 1], xd, w.y);
            }
        }
    }

    int c = colbase + lane * 4;
    float* OUT; int cc;
    if (c < M) { OUT = XL; cc = c; } else { OUT = XR; cc = c - M; }
#pragma unroll
    for (int r = 0; r < 8; r++) {
        int row = row0 + wrow + r;
        if (row < n) {
            union { ull u[2]; float4 f; } t;
            t.u[0] = acc[r * 2];
            t.u[1] = acc[r * 2 + 1];
            *(float4*)&OUT[(size_t)row * M + cc] = t.f;
        }
    }
}

// ---------------- GATv2 aggregation ----------------
template <int HC, int H>
__global__ void k_gat(const float* __restrict__ XL, const float* __restrict__ XR,
                      const int* __restrict__ rowptr, const int* __restrict__ col,
                      const float* __restrict__ att, const float* __restrict__ bias,
                      float* __restrict__ Y, int n) {
    constexpr int V  = HC / 32;
    constexpr int GW = 32 / H;
    const int lane = threadIdx.x & 31;
    const int node = blockIdx.x * (blockDim.x >> 5) + (threadIdx.x >> 5);
    if (node >= n) return;

    float attv[V], bv[V], xr[V], acc[V];
#pragma unroll
    for (int v = 0; v < V; v++) {
        attv[v] = att[lane * V + v];
        bv[v]   = bias[lane * V + v];
        acc[v]  = 0.f;
    }
    {
        const float* p = XR + (size_t)node * HC + lane * V;
        if (V == 4) { float4 t = *(const float4*)p; xr[0]=t.x; xr[1]=t.y; xr[2]=t.z; xr[3]=t.w; }
        else        { float2 t = *(const float2*)p; xr[0]=t.x; xr[1]=t.y; }
    }

    const int e0 = rowptr[node], e1 = rowptr[node + 1];
    float nb[V];
    {
        int s = __ldg(&col[e0]);
        const float* p = XL + (size_t)s * HC + lane * V;
        if (V == 4) { float4 t = *(const float4*)p; nb[0]=t.x; nb[1]=t.y; nb[2]=t.z; nb[3]=t.w; }
        else        { float2 t = *(const float2*)p; nb[0]=t.x; nb[1]=t.y; }
    }

    float m = -3.0e38f, den = 0.f;
    for (int e = e0; e < e1; e++) {
        float xl[V];
#pragma unroll
        for (int v = 0; v < V; v++) xl[v] = nb[v];
        if (e + 1 < e1) {
            int s2 = __ldg(&col[e + 1]);
            const float* p = XL + (size_t)s2 * HC + lane * V;
            if (V == 4) { float4 t = *(const float4*)p; nb[0]=t.x; nb[1]=t.y; nb[2]=t.z; nb[3]=t.w; }
            else        { float2 t = *(const float2*)p; nb[0]=t.x; nb[1]=t.y; }
        }
        float pscore = 0.f;
#pragma unroll
        for (int v = 0; v < V; v++) {
            float t = xl[v] + xr[v];
            t = (t > 0.f) ? t : 0.2f * t;
            pscore = fmaf(attv[v], t, pscore);
        }
#pragma unroll
        for (int off = GW >> 1; off > 0; off >>= 1)
            pscore += __shfl_xor_sync(0xffffffffu, pscore, off);

        float mn   = fmaxf(m, pscore);
        float corr = __expf(m - mn);
        float w    = __expf(pscore - mn);
        den = den * corr + w;
#pragma unroll
        for (int v = 0; v < V; v++) acc[v] = fmaf(acc[v], corr, w * xl[v]);
        m = mn;
    }

    float inv = 1.f / den;
    float* yp = Y + (size_t)node * HC + lane * V;
#pragma unroll
    for (int v = 0; v < V; v++) {
        float y = fmaf(acc[v], inv, bv[v]);
        yp[v] = (y > 0.f) ? y : 0.2f * y;
    }
}

// ---------------- global mean pool (run-length aggregated; batch is sorted) ----------------
__global__ void k_zero_pool(float* out, float* cnt) {
    int i = blockIdx.x * blockDim.x + threadIdx.x;
    if (i < GG * 64) out[i] = 0.f;
    if (i < GG) cnt[i] = 0.f;
}

#define PCH 256
__global__ void k_pool2(const float* __restrict__ X, const int* __restrict__ batch,
                        float* out, float* cnt, int n) {
    const int f = threadIdx.x;  // 0..63
    const int chunk = blockIdx.x * blockDim.y + threadIdx.y;
    const int n0 = chunk * PCH;
    if (n0 >= n) return;
    const int n1 = min(n, n0 + PCH);
    int curg = __ldg(&batch[n0]);
    float acc = 0.f, c = 0.f;
    for (int node = n0; node < n1; node++) {
        int g = __ldg(&batch[node]);
        if (g != curg) {
            atomicAdd(&out[curg * 64 + f], acc);
            if (f == 0) atomicAdd(&cnt[curg], c);
            acc = 0.f; c = 0.f; curg = g;
        }
        acc += X[(size_t)node * 64 + f];
        c += 1.f;
    }
    atomicAdd(&out[curg * 64 + f], acc);
    if (f == 0) atomicAdd(&cnt[curg], c);
}

__global__ void k_fin(float* out, const float* __restrict__ cnt) {
    int i = blockIdx.x * blockDim.x + threadIdx.x;
    if (i < GG * 64) out[i] /= fmaxf(cnt[i >> 6], 1.f);
}

// ---------------- launch ----------------
extern "C" void kernel_launch(void* const* d_in, const int* in_sizes, int n_in,
                              void* d_out, int out_size) {
    const float* x     = (const float*)d_in[0];
    const int*   ei    = (const int*)d_in[1];
    const int*   batch = (const int*)d_in[2];
    const float* Wl0 = (const float*)d_in[3];
    const float* Wr0 = (const float*)d_in[4];
    const float* at0 = (const float*)d_in[5];
    const float* b0  = (const float*)d_in[6];
    const float* Wl1 = (const float*)d_in[7];
    const float* Wr1 = (const float*)d_in[8];
    const float* at1 = (const float*)d_in[9];
    const float* b1  = (const float*)d_in[10];
    const float* Wl2 = (const float*)d_in[11];
    const float* Wr2 = (const float*)d_in[12];
    const float* at2 = (const float*)d_in[13];
    const float* b2  = (const float*)d_in[14];
    float* out = (float*)d_out;

    const int n = in_sizes[2];
    const int e = in_sizes[1] / 2;
    const int* src = ei;
    const int* tgt = ei + e;

    float *pXL, *pXR, *pBA, *pBB, *pcnt;
    int *prow, *ptmp, *pcol, *plscan, *pbsum;
    cudaGetSymbolAddress((void**)&pXL, g_XL);
    cudaGetSymbolAddress((void**)&pXR, g_XR);
    cudaGetSymbolAddress((void**)&pBA, g_BA);
    cudaGetSymbolAddress((void**)&pBB, g_BB);
    cudaGetSymbolAddress((void**)&prow, g_rowptr);
    cudaGetSymbolAddress((void**)&ptmp, g_tmp);
    cudaGetSymbolAddress((void**)&pcol, g_col);
    cudaGetSymbolAddress((void**)&plscan, g_lscan);
    cudaGetSymbolAddress((void**)&pbsum, g_bsum);
    cudaGetSymbolAddress((void**)&pcnt, g_cnt);

    const int smem = 64 * 128 * 8 + 64 * 128 * 4;  // 96 KB
    cudaFuncSetAttribute(k_gemm2<128>, cudaFuncAttributeMaxDynamicSharedMemorySize, smem);
    cudaFuncSetAttribute(k_gemm2<64>,  cudaFuncAttributeMaxDynamicSharedMemorySize, smem);

    const int grows   = (n + 63) / 64;
    const int ablocks = (n + 7) / 8;
    const int nsb     = (n + SCHUNK - 1) / SCHUNK;  // scan blocks (98)

    // CSR counts
    k_init_counts<<<(n + 255) / 256, 256>>>(ptmp, n);
    k_hist<<<(e + 255) / 256, 256>>>(tgt, ptmp, e);
    k_scanA<<<nsb, SCHUNK>>>(ptmp, plscan, pbsum, n);

    // layer-0 fused GEMM (independent of CSR) — positioned so ncu capture lands here
    k_gemm2<128><<<dim3(grows, 2), 256, smem>>>(x, Wl0, Wr0, pXL, pXR, n);

    k_scanB<<<1, 128>>>(pbsum, nsb);
    k_scanC<<<(n + 255) / 256, 256>>>(ptmp, plscan, pbsum, prow, n);
    k_scatter<<<(e + n + 255) / 256, 256>>>(src, tgt, ptmp, pcol, e, n);

    // layer 0 aggregate
    k_gat<128, 4><<<ablocks, 256>>>(pXL, pXR, prow, pcol, at0, b0, pBA, n);

    // layer 1
    k_gemm2<128><<<dim3(grows, 2), 256, smem>>>(pBA, Wl1, Wr1, pXL, pXR, n);
    k_gat<128, 4><<<ablocks, 256>>>(pXL, pXR, prow, pcol, at1, b1, pBB, n);

    // layer 2 (1 head x 64)
    k_gemm2<64><<<dim3(grows, 1), 256, smem>>>(pBB, Wl2, Wr2, pXL, pXR, n);
    k_gat<64, 1><<<ablocks, 256>>>(pXL, pXR, prow, pcol, at2, b2, pBA, n);

    // global mean pool
    k_zero_pool<<<(GG * 64 + 255) / 256, 256>>>(out, pcnt);
    {
        dim3 blk(64, 4);
        int pblocks = (n + PCH * 4 - 1) / (PCH * 4);
        k_pool2<<<pblocks, blk>>>(pBA, batch, out, pcnt, n);
    }
    k_fin<<<(GG * 64 + 255) / 256, 256>>>(out, pcnt);
}

// round 5
// speedup vs baseline: 5.5236x; 1.2526x over previous
#include <cuda_runtime.h>
#include <cuda_bf16.h>
#include <math.h>

#define NN 50000
#define EE 800000
#define GG 64
#define ETOT (EE + NN)
#define SCHUNK 512

typedef unsigned long long ull;
typedef unsigned int u32;
typedef unsigned short u16;

// ---------------- static device scratch ----------------
__device__ float g_XL[NN * 128];
__device__ float g_XR[NN * 128];
__device__ float g_BA[NN * 128];
__device__ float g_BB[NN * 128];
__device__ int   g_rowptr[NN + 1];
__device__ int   g_tmp[NN];
__device__ int   g_lscan[NN];
__device__ int   g_bsum[256];
__device__ int   g_col[ETOT];
__device__ float g_cnt[GG];
__device__ u16   g_Bhi[256 * 128];   // pre-swizzled bf16 weight image (hi)
__device__ u16   g_Blo[256 * 128];   // pre-swizzled bf16 weight image (lo)

// ---------------- helpers ----------------
__device__ __forceinline__ u32 smem_u32(const void* p) {
    u32 a;
    asm("{ .reg .u64 t; cvta.to.shared.u64 t, %1; cvt.u32.u64 %0, t; }" : "=r"(a) : "l"(p));
    return a;
}

__device__ __forceinline__ u32 pack_bf16x2(float lo, float hi) {
    u32 r;
    asm("cvt.rn.bf16x2.f32 %0, %1, %2;" : "=r"(r) : "f"(hi), "f"(lo));
    return r;
}

// XOR-swizzled byte offset inside a [rows][128 bf16] tile (256B rows, 16B chunks)
__device__ __forceinline__ u32 swz_off(int r, int k) {
    int chunk = k >> 3;
    return (u32)(r * 256 + (((chunk ^ (r & 7)) & 15) << 4) + (k & 7) * 2);
}

__device__ __forceinline__ void ldmx4(u32& r0, u32& r1, u32& r2, u32& r3, u32 addr) {
    asm volatile("ldmatrix.sync.aligned.m8n8.x4.shared.b16 {%0,%1,%2,%3}, [%4];"
                 : "=r"(r0), "=r"(r1), "=r"(r2), "=r"(r3) : "r"(addr));
}

__device__ __forceinline__ void mma_bf16(float* c, const u32* a, const u32* b) {
    asm volatile("mma.sync.aligned.m16n8k16.row.col.f32.bf16.bf16.f32 "
                 "{%0,%1,%2,%3}, {%4,%5,%6,%7}, {%8,%9}, {%0,%1,%2,%3};"
                 : "+f"(c[0]), "+f"(c[1]), "+f"(c[2]), "+f"(c[3])
                 : "r"(a[0]), "r"(a[1]), "r"(a[2]), "r"(a[3]), "r"(b[0]), "r"(b[1]));
}

// ---------------- weight prep: transpose + bf16 split + pre-swizzle ----------------
// image rows 0..M-1 = Wl columns, rows M..2M-1 = Wr columns; each row = 128 K-values
__global__ void k_prep(const float* __restrict__ Wl, const float* __restrict__ Wr,
                       u16* __restrict__ Bhi, u16* __restrict__ Blo, int M, int Nrows) {
    int i = blockIdx.x * blockDim.x + threadIdx.x;
    if (i >= Nrows * 128) return;
    int r = i >> 7, k = i & 127;
    float v = (r < M) ? Wl[k * M + r] : Wr[k * M + r - M];
    __nv_bfloat16 h = __float2bfloat16(v);
    float hf = __bfloat162float(h);
    __nv_bfloat16 l = __float2bfloat16(v - hf);
    u32 off = swz_off(r, k) >> 1;   // u16 index
    Bhi[off] = *(u16*)&h;
    Blo[off] = *(u16*)&l;
}

// ---------------- HMMA dual GEMM: block 128 rows x 128 cols, K=128, bf16-split ----------------
#define SA_HI 0
#define SA_LO 32768
#define SB_HI 65536
#define SB_LO 98304
#define GSMEM 131072

__global__ __launch_bounds__(256)
void k_gemm_hmma(const float* __restrict__ X, const u16* __restrict__ Bimg_hi,
                 const u16* __restrict__ Bimg_lo, float* __restrict__ XL,
                 float* __restrict__ XR, int n, int M) {
    extern __shared__ char smem[];
    const u32 sb = smem_u32(smem);
    const int tid = threadIdx.x, wid = tid >> 5, lane = tid & 31;
    const int row0 = blockIdx.x * 128;
    const int cb0 = blockIdx.y * 128;   // global col base of this block

    // ---- A tile: fp32 -> bf16 hi/lo, swizzled
    for (int i = tid; i < 128 * 64; i += 256) {
        int row = i >> 6;
        int kp = (i & 63) * 2;
        float2 v = make_float2(0.f, 0.f);
        if (row0 + row < n) v = *(const float2*)&X[(size_t)(row0 + row) * 128 + kp];
        u32 hi = pack_bf16x2(v.x, v.y);
        float h0 = __uint_as_float(hi << 16);
        float h1 = __uint_as_float(hi & 0xffff0000u);
        u32 lo = pack_bf16x2(v.x - h0, v.y - h1);
        u32 off = swz_off(row, kp);
        *(u32*)(smem + SA_HI + off) = hi;
        *(u32*)(smem + SA_LO + off) = lo;
    }
    // ---- B tiles: raw copy of pre-swizzled image chunk (rows cb0..cb0+127)
    {
        const uint4* bh = (const uint4*)(Bimg_hi + (size_t)cb0 * 128);
        const uint4* bl = (const uint4*)(Bimg_lo + (size_t)cb0 * 128);
        uint4* sh = (uint4*)(smem + SB_HI);
        uint4* sl = (uint4*)(smem + SB_LO);
        for (int i = tid; i < 32768 / 16; i += 256) {
            sh[i] = __ldg(&bh[i]);
            sl[i] = __ldg(&bl[i]);
        }
    }
    __syncthreads();

    const int warp_m = wid & 3;       // 4 warps over 128 rows (32 each)
    const int warp_n = wid >> 2;      // 2 warps over 128 cols (64 each)

    float acc[2][8][4];
#pragma unroll
    for (int t = 0; t < 2; t++)
#pragma unroll
        for (int j = 0; j < 8; j++)
#pragma unroll
            for (int c = 0; c < 4; c++) acc[t][j][c] = 0.f;

    // per-lane ldmatrix source rows
    const int arow = warp_m * 32 + (lane & 15);     // + t*16
    const int akh  = lane >> 4;                     // k half (0/1)
    const int nrow = warp_n * 64 + ((lane >> 4) & 1) * 8 + (lane & 7);  // + jj*16
    const int bkh  = (lane >> 3) & 1;

#pragma unroll
    for (int ks = 0; ks < 8; ks++) {
        u32 ahi[2][4], alo[2][4], bhi[8][2], blo[8][2];
#pragma unroll
        for (int t = 0; t < 2; t++) {
            int r = arow + t * 16;
            u32 off = (u32)(r * 256 + ((((ks * 2 + akh) ^ (r & 7)) & 15) << 4));
            ldmx4(ahi[t][0], ahi[t][1], ahi[t][2], ahi[t][3], sb + SA_HI + off);
            ldmx4(alo[t][0], alo[t][1], alo[t][2], alo[t][3], sb + SA_LO + off);
        }
#pragma unroll
        for (int jj = 0; jj < 4; jj++) {
            int r = nrow + jj * 16;
            u32 off = (u32)(r * 256 + ((((ks * 2 + bkh) ^ (r & 7)) & 15) << 4));
            ldmx4(bhi[jj * 2][0], bhi[jj * 2][1], bhi[jj * 2 + 1][0], bhi[jj * 2 + 1][1],
                  sb + SB_HI + off);
            ldmx4(blo[jj * 2][0], blo[jj * 2][1], blo[jj * 2 + 1][0], blo[jj * 2 + 1][1],
                  sb + SB_LO + off);
        }
#pragma unroll
        for (int t = 0; t < 2; t++)
#pragma unroll
            for (int j = 0; j < 8; j++) {
                mma_bf16(acc[t][j], ahi[t], bhi[j]);
                mma_bf16(acc[t][j], alo[t], bhi[j]);
                mma_bf16(acc[t][j], ahi[t], blo[j]);
            }
    }

    // ---- epilogue: fragment -> XL/XR
    const int cwb = cb0 + warp_n * 64;  // warp col base (entirely within one half)
    float* OUT = (cwb < M) ? XL : XR;
    const int cof = (cwb < M) ? cwb : cwb - M;
#pragma unroll
    for (int t = 0; t < 2; t++) {
        int r = row0 + warp_m * 32 + t * 16 + (lane >> 2);
#pragma unroll
        for (int j = 0; j < 8; j++) {
            int c = cof + j * 8 + (lane & 3) * 2;
            if (r < n)
                *(float2*)&OUT[(size_t)r * M + c] = make_float2(acc[t][j][0], acc[t][j][1]);
            if (r + 8 < n)
                *(float2*)&OUT[(size_t)(r + 8) * M + c] = make_float2(acc[t][j][2], acc[t][j][3]);
        }
    }
}

// ---------------- CSR build ----------------
__global__ void k_init_counts(int* cnt, int n) {
    int i = blockIdx.x * blockDim.x + threadIdx.x;
    if (i < n) cnt[i] = 1;
}

__global__ void k_hist(const int* __restrict__ tgt, int* cnt, int e) {
    int i = blockIdx.x * blockDim.x + threadIdx.x;
    if (i < e) atomicAdd(&cnt[tgt[i]], 1);
}

__global__ void k_scanA(const int* __restrict__ counts, int* __restrict__ lscan,
                        int* __restrict__ bsum, int n) {
    __shared__ int wsum[16];
    const int tid = threadIdx.x, lane = tid & 31, wid = tid >> 5;
    const int i = blockIdx.x * SCHUNK + tid;
    int v = (i < n) ? counts[i] : 0;
    int incl = v;
#pragma unroll
    for (int off = 1; off < 32; off <<= 1) {
        int t = __shfl_up_sync(0xffffffffu, incl, off);
        if (lane >= off) incl += t;
    }
    if (lane == 31) wsum[wid] = incl;
    __syncthreads();
    if (tid < 16) {
        int w = wsum[tid];
        int s = w;
#pragma unroll
        for (int off = 1; off < 16; off <<= 1) {
            int t = __shfl_up_sync(0xffffu, s, off);
            if (tid >= off) s += t;
        }
        wsum[tid] = s - w;
    }
    __syncthreads();
    incl += wsum[wid];
    if (i < n) lscan[i] = incl;
    if (tid == SCHUNK - 1) bsum[blockIdx.x] = incl;
}

__global__ void k_scanB(int* bsum, int nb) {
    __shared__ int wsum[4];
    const int tid = threadIdx.x, lane = tid & 31, wid = tid >> 5;
    int v = (tid < nb) ? bsum[tid] : 0;
    int incl = v;
#pragma unroll
    for (int off = 1; off < 32; off <<= 1) {
        int t = __shfl_up_sync(0xffffffffu, incl, off);
        if (lane >= off) incl += t;
    }
    if (lane == 31) wsum[wid] = incl;
    __syncthreads();
    int base = 0;
    for (int w = 0; w < wid; w++) base += wsum[w];
    if (tid < nb) bsum[tid] = base + incl - v;
}

__global__ void k_scanC(int* __restrict__ counts_cursor, const int* __restrict__ lscan,
                        const int* __restrict__ bsum, int* __restrict__ rowptr, int n) {
    int i = blockIdx.x * blockDim.x + threadIdx.x;
    if (i < n) {
        int c = counts_cursor[i];
        int incl = bsum[i / SCHUNK] + lscan[i];
        rowptr[i + 1] = incl;
        counts_cursor[i] = incl - c;
    }
    if (i == 0) rowptr[0] = 0;
}

__global__ void k_scatter(const int* __restrict__ src, const int* __restrict__ tgt,
                          int* wcur, int* col, int e, int n) {
    int i = blockIdx.x * blockDim.x + threadIdx.x;
    if (i < e) {
        int d = tgt[i];
        int p = atomicAdd(&wcur[d], 1);
        col[p] = src[i];
    } else if (i < e + n) {
        int v = i - e;
        int p = atomicAdd(&wcur[v], 1);
        col[p] = v;
    }
}

// ---------------- GATv2 aggregation ----------------
template <int HC, int H>
__global__ void k_gat(const float* __restrict__ XL, const float* __restrict__ XR,
                      const int* __restrict__ rowptr, const int* __restrict__ col,
                      const float* __restrict__ att, const float* __restrict__ bias,
                      float* __restrict__ Y, int n) {
    constexpr int V  = HC / 32;
    constexpr int GW = 32 / H;
    const int lane = threadIdx.x & 31;
    const int node = blockIdx.x * (blockDim.x >> 5) + (threadIdx.x >> 5);
    if (node >= n) return;

    float attv[V], bv[V], xr[V], acc[V];
#pragma unroll
    for (int v = 0; v < V; v++) {
        attv[v] = att[lane * V + v];
        bv[v]   = bias[lane * V + v];
        acc[v]  = 0.f;
    }
    {
        const float* p = XR + (size_t)node * HC + lane * V;
        if (V == 4) { float4 t = *(const float4*)p; xr[0]=t.x; xr[1]=t.y; xr[2]=t.z; xr[3]=t.w; }
        else        { float2 t = *(const float2*)p; xr[0]=t.x; xr[1]=t.y; }
    }

    const int e0 = rowptr[node], e1 = rowptr[node + 1];
    float nb[V];
    {
        int s = __ldg(&col[e0]);
        const float* p = XL + (size_t)s * HC + lane * V;
        if (V == 4) { float4 t = *(const float4*)p; nb[0]=t.x; nb[1]=t.y; nb[2]=t.z; nb[3]=t.w; }
        else        { float2 t = *(const float2*)p; nb[0]=t.x; nb[1]=t.y; }
    }

    float m = -3.0e38f, den = 0.f;
    for (int e = e0; e < e1; e++) {
        float xl[V];
#pragma unroll
        for (int v = 0; v < V; v++) xl[v] = nb[v];
        if (e + 1 < e1) {
            int s2 = __ldg(&col[e + 1]);
            const float* p = XL + (size_t)s2 * HC + lane * V;
            if (V == 4) { float4 t = *(const float4*)p; nb[0]=t.x; nb[1]=t.y; nb[2]=t.z; nb[3]=t.w; }
            else        { float2 t = *(const float2*)p; nb[0]=t.x; nb[1]=t.y; }
        }
        float pscore = 0.f;
#pragma unroll
        for (int v = 0; v < V; v++) {
            float t = xl[v] + xr[v];
            t = (t > 0.f) ? t : 0.2f * t;
            pscore = fmaf(attv[v], t, pscore);
        }
#pragma unroll
        for (int off = GW >> 1; off > 0; off >>= 1)
            pscore += __shfl_xor_sync(0xffffffffu, pscore, off);

        float mn   = fmaxf(m, pscore);
        float corr = __expf(m - mn);
        float w    = __expf(pscore - mn);
        den = den * corr + w;
#pragma unroll
        for (int v = 0; v < V; v++) acc[v] = fmaf(acc[v], corr, w * xl[v]);
        m = mn;
    }

    float inv = 1.f / den;
    float* yp = Y + (size_t)node * HC + lane * V;
#pragma unroll
    for (int v = 0; v < V; v++) {
        float y = fmaf(acc[v], inv, bv[v]);
        yp[v] = (y > 0.f) ? y : 0.2f * y;
    }
}

// ---------------- global mean pool ----------------
__global__ void k_zero_pool(float* out, float* cnt) {
    int i = blockIdx.x * blockDim.x + threadIdx.x;
    if (i < GG * 64) out[i] = 0.f;
    if (i < GG) cnt[i] = 0.f;
}

#define PCH 256
__global__ void k_pool2(const float* __restrict__ X, const int* __restrict__ batch,
                        float* out, float* cnt, int n) {
    const int f = threadIdx.x;
    const int chunk = blockIdx.x * blockDim.y + threadIdx.y;
    const int n0 = chunk * PCH;
    if (n0 >= n) return;
    const int n1 = min(n, n0 + PCH);
    int curg = __ldg(&batch[n0]);
    float acc = 0.f, c = 0.f;
    for (int node = n0; node < n1; node++) {
        int g = __ldg(&batch[node]);
        if (g != curg) {
            atomicAdd(&out[curg * 64 + f], acc);
            if (f == 0) atomicAdd(&cnt[curg], c);
            acc = 0.f; c = 0.f; curg = g;
        }
        acc += X[(size_t)node * 64 + f];
        c += 1.f;
    }
    atomicAdd(&out[curg * 64 + f], acc);
    if (f == 0) atomicAdd(&cnt[curg], c);
}

__global__ void k_fin(float* out, const float* __restrict__ cnt) {
    int i = blockIdx.x * blockDim.x + threadIdx.x;
    if (i < GG * 64) out[i] /= fmaxf(cnt[i >> 6], 1.f);
}

// ---------------- launch ----------------
extern "C" void kernel_launch(void* const* d_in, const int* in_sizes, int n_in,
                              void* d_out, int out_size) {
    const float* x     = (const float*)d_in[0];
    const int*   ei    = (const int*)d_in[1];
    const int*   batch = (const int*)d_in[2];
    const float* Wl0 = (const float*)d_in[3];
    const float* Wr0 = (const float*)d_in[4];
    const float* at0 = (const float*)d_in[5];
    const float* b0  = (const float*)d_in[6];
    const float* Wl1 = (const float*)d_in[7];
    const float* Wr1 = (const float*)d_in[8];
    const float* at1 = (const float*)d_in[9];
    const float* b1  = (const float*)d_in[10];
    const float* Wl2 = (const float*)d_in[11];
    const float* Wr2 = (const float*)d_in[12];
    const float* at2 = (const float*)d_in[13];
    const float* b2  = (const float*)d_in[14];
    float* out = (float*)d_out;

    const int n = in_sizes[2];
    const int e = in_sizes[1] / 2;
    const int* src = ei;
    const int* tgt = ei + e;

    float *pXL, *pXR, *pBA, *pBB, *pcnt;
    int *prow, *ptmp, *pcol, *plscan, *pbsum;
    u16 *pBhi, *pBlo;
    cudaGetSymbolAddress((void**)&pXL, g_XL);
    cudaGetSymbolAddress((void**)&pXR, g_XR);
    cudaGetSymbolAddress((void**)&pBA, g_BA);
    cudaGetSymbolAddress((void**)&pBB, g_BB);
    cudaGetSymbolAddress((void**)&prow, g_rowptr);
    cudaGetSymbolAddress((void**)&ptmp, g_tmp);
    cudaGetSymbolAddress((void**)&pcol, g_col);
    cudaGetSymbolAddress((void**)&plscan, g_lscan);
    cudaGetSymbolAddress((void**)&pbsum, g_bsum);
    cudaGetSymbolAddress((void**)&pcnt, g_cnt);
    cudaGetSymbolAddress((void**)&pBhi, g_Bhi);
    cudaGetSymbolAddress((void**)&pBlo, g_Blo);

    cudaFuncSetAttribute(k_gemm_hmma, cudaFuncAttributeMaxDynamicSharedMemorySize, GSMEM);

    const int gtiles  = (n + 127) / 128;  // 391
    const int ablocks = (n + 7) / 8;
    const int nsb     = (n + SCHUNK - 1) / SCHUNK;

    // layer-0 weight prep + CSR counts; GEMM positioned 4th for ncu capture
    k_prep<<<128, 256>>>(Wl0, Wr0, pBhi, pBlo, 128, 256);
    k_init_counts<<<(n + 255) / 256, 256>>>(ptmp, n);
    k_hist<<<(e + 255) / 256, 256>>>(tgt, ptmp, e);
    k_gemm_hmma<<<dim3(gtiles, 2), 256, GSMEM>>>(x, pBhi, pBlo, pXL, pXR, n, 128);

    k_scanA<<<nsb, SCHUNK>>>(ptmp, plscan, pbsum, n);
    k_scanB<<<1, 128>>>(pbsum, nsb);
    k_scanC<<<(n + 255) / 256, 256>>>(ptmp, plscan, pbsum, prow, n);
    k_scatter<<<(e + n + 255) / 256, 256>>>(src, tgt, ptmp, pcol, e, n);

    // layer 0 aggregate
    k_gat<128, 4><<<ablocks, 256>>>(pXL, pXR, prow, pcol, at0, b0, pBA, n);

    // layer 1
    k_prep<<<128, 256>>>(Wl1, Wr1, pBhi, pBlo, 128, 256);
    k_gemm_hmma<<<dim3(gtiles, 2), 256, GSMEM>>>(pBA, pBhi, pBlo, pXL, pXR, n, 128);
    k_gat<128, 4><<<ablocks, 256>>>(pXL, pXR, prow, pcol, at1, b1, pBB, n);

    // layer 2 (1 head x 64): image 128 rows (Wl|Wr), M=64
    k_prep<<<64, 256>>>(Wl2, Wr2, pBhi, pBlo, 64, 128);
    k_gemm_hmma<<<dim3(gtiles, 1), 256, GSMEM>>>(pBB, pBhi, pBlo, pXL, pXR, n, 64);
    k_gat<64, 1><<<ablocks, 256>>>(pXL, pXR, prow, pcol, at2, b2, pBA, n);

    // global mean pool
    k_zero_pool<<<(GG * 64 + 255) / 256, 256>>>(out, pcnt);
    {
        dim3 blk(64, 4);
        int pblocks = (n + PCH * 4 - 1) / (PCH * 4);
        k_pool2<<<pblocks, blk>>>(pBA, batch, out, pcnt, n);
    }
    k_fin<<<(GG * 64 + 255) / 256, 256>>>(out, pcnt);
}

// round 6
// speedup vs baseline: 6.4254x; 1.1633x over previous
#include <cuda_runtime.h>
#include <cuda_bf16.h>
#include <math.h>

#define NN 50000
#define EE 800000
#define GG 64
#define ETOT (EE + NN)
#define SCHUNK 512

typedef unsigned long long ull;
typedef unsigned int u32;
typedef unsigned short u16;

// ---------------- static device scratch ----------------
__device__ float g_XL[NN * 128];
__device__ float g_XR[NN * 128];
__device__ float g_BA[NN * 128];
__device__ float g_BB[NN * 128];
__device__ int   g_rowptr[NN + 1];
__device__ int   g_tmp[NN];
__device__ int   g_lscan[NN];
__device__ int   g_bsum[256];
__device__ int   g_col[ETOT];
__device__ float g_cnt[GG];
__device__ u16   g_Bhi[256 * 128];   // pre-swizzled bf16 weight image (hi)
__device__ u16   g_Blo[256 * 128];   // pre-swizzled bf16 weight image (lo)

// ---------------- helpers ----------------
__device__ __forceinline__ u32 smem_u32(const void* p) {
    u32 a;
    asm("{ .reg .u64 t; cvta.to.shared.u64 t, %1; cvt.u32.u64 %0, t; }" : "=r"(a) : "l"(p));
    return a;
}

__device__ __forceinline__ u32 pack_bf16x2(float lo, float hi) {
    u32 r;
    asm("cvt.rn.bf16x2.f32 %0, %1, %2;" : "=r"(r) : "f"(hi), "f"(lo));
    return r;
}

// XOR-swizzled byte offset inside a [rows][128 bf16] tile (256B rows, 16B chunks)
__device__ __forceinline__ u32 swz_off(int r, int k) {
    int chunk = k >> 3;
    return (u32)(r * 256 + (((chunk ^ (r & 7)) & 15) << 4) + (k & 7) * 2);
}

__device__ __forceinline__ void ldmx4(u32& r0, u32& r1, u32& r2, u32& r3, u32 addr) {
    asm volatile("ldmatrix.sync.aligned.m8n8.x4.shared.b16 {%0,%1,%2,%3}, [%4];"
                 : "=r"(r0), "=r"(r1), "=r"(r2), "=r"(r3) : "r"(addr));
}

__device__ __forceinline__ void mma_bf16(float* c, const u32* a, const u32* b) {
    asm volatile("mma.sync.aligned.m16n8k16.row.col.f32.bf16.bf16.f32 "
                 "{%0,%1,%2,%3}, {%4,%5,%6,%7}, {%8,%9}, {%0,%1,%2,%3};"
                 : "+f"(c[0]), "+f"(c[1]), "+f"(c[2]), "+f"(c[3])
                 : "r"(a[0]), "r"(a[1]), "r"(a[2]), "r"(a[3]), "r"(b[0]), "r"(b[1]));
}

__device__ __forceinline__ void cp16(u32 s, const void* g) {
    asm volatile("{ .reg .u64 t; cvta.to.global.u64 t, %1; "
                 "cp.async.cg.shared.global [%0], [t], 16; }" :: "r"(s), "l"(g));
}
#define CP_COMMIT() asm volatile("cp.async.commit_group;" ::: "memory")
#define CP_WAIT0()  asm volatile("cp.async.wait_group 0;" ::: "memory")

// ---------------- weight prep: transpose + bf16 split + pre-swizzle ----------------
__global__ void k_prep(const float* __restrict__ Wl, const float* __restrict__ Wr,
                       u16* __restrict__ Bhi, u16* __restrict__ Blo, int M, int Nrows) {
    int i = blockIdx.x * blockDim.x + threadIdx.x;
    if (i >= Nrows * 128) return;
    int r = i >> 7, k = i & 127;
    float v = (r < M) ? Wl[k * M + r] : Wr[k * M + r - M];
    __nv_bfloat16 h = __float2bfloat16(v);
    float hf = __bfloat162float(h);
    __nv_bfloat16 l = __float2bfloat16(v - hf);
    u32 off = swz_off(r, k) >> 1;
    Bhi[off] = *(u16*)&h;
    Blo[off] = *(u16*)&l;
}

// ---------------- HMMA dual GEMM: 64 rows x 128 cols per block, K=128, bf16-split ----
// A loaded straight from gmem into fragments (no smem); B from pre-swizzled image via cp.async.
#define SB_HI 0
#define SB_LO 32768
#define GSMEM 65536

__global__ __launch_bounds__(256, 2)
void k_gemm_hmma(const float* __restrict__ X, const u16* __restrict__ Bimg_hi,
                 const u16* __restrict__ Bimg_lo, float* __restrict__ XL,
                 float* __restrict__ XR, int n, int M) {
    extern __shared__ char smem[];
    const u32 sb = smem_u32(smem);
    const int tid = threadIdx.x, wid = tid >> 5, lane = tid & 31;
    const int row0 = blockIdx.x * 64;
    const int cb0 = blockIdx.y * 128;

    // ---- B tiles via cp.async (32KB hi + 32KB lo)
    {
        const char* bh = (const char*)(Bimg_hi + (size_t)cb0 * 128);
        const char* bl = (const char*)(Bimg_lo + (size_t)cb0 * 128);
        for (int i = tid * 16; i < 32768; i += 256 * 16) {
            cp16(sb + SB_HI + i, bh + i);
            cp16(sb + SB_LO + i, bl + i);
        }
        CP_COMMIT();
    }

    const int warp_m = wid & 3;     // 4 warps x 16 rows
    const int warp_n = wid >> 2;    // 2 warps x 64 cols
    const int gr = row0 + warp_m * 16 + (lane >> 2);
    const bool ok0 = gr < n, ok1 = gr + 8 < n;
    const float* Xr0 = X + (size_t)gr * 128 + (lane & 3) * 2;
    const float* Xr1 = Xr0 + 8 * 128;
    const int nrowb = warp_n * 64 + ((lane >> 4) & 1) * 8 + (lane & 7);
    const int bkh = (lane >> 3) & 1;

    float acc[8][4];
#pragma unroll
    for (int j = 0; j < 8; j++)
#pragma unroll
        for (int c = 0; c < 4; c++) acc[j][c] = 0.f;

    float2 raw[4];
    // prefetch ks=0
    raw[0] = ok0 ? *(const float2*)Xr0 : make_float2(0.f, 0.f);
    raw[1] = ok1 ? *(const float2*)Xr1 : make_float2(0.f, 0.f);
    raw[2] = ok0 ? *(const float2*)(Xr0 + 8) : make_float2(0.f, 0.f);
    raw[3] = ok1 ? *(const float2*)(Xr1 + 8) : make_float2(0.f, 0.f);

    CP_WAIT0();
    __syncthreads();

#pragma unroll
    for (int ks = 0; ks < 8; ks++) {
        float2 nxt[4];
        if (ks < 7) {
            const float* p0 = Xr0 + (ks + 1) * 16;
            const float* p1 = Xr1 + (ks + 1) * 16;
            nxt[0] = ok0 ? *(const float2*)p0 : make_float2(0.f, 0.f);
            nxt[1] = ok1 ? *(const float2*)p1 : make_float2(0.f, 0.f);
            nxt[2] = ok0 ? *(const float2*)(p0 + 8) : make_float2(0.f, 0.f);
            nxt[3] = ok1 ? *(const float2*)(p1 + 8) : make_float2(0.f, 0.f);
        }
        // convert to bf16 hi/lo fragments
        u32 ahi[4], alo[4];
#pragma unroll
        for (int q = 0; q < 4; q++) {
            u32 h = pack_bf16x2(raw[q].x, raw[q].y);
            ahi[q] = h;
            float h0 = __uint_as_float(h << 16);
            float h1 = __uint_as_float(h & 0xffff0000u);
            alo[q] = pack_bf16x2(raw[q].x - h0, raw[q].y - h1);
        }
#pragma unroll
        for (int jj = 0; jj < 4; jj++) {
            int r = nrowb + jj * 16;
            u32 off = (u32)(r * 256 + ((((ks * 2 + bkh) ^ (r & 7)) & 15) << 4));
            u32 bh[4], bl[4];
            ldmx4(bh[0], bh[1], bh[2], bh[3], sb + SB_HI + off);
            ldmx4(bl[0], bl[1], bl[2], bl[3], sb + SB_LO + off);
            mma_bf16(acc[jj * 2], ahi, bh);
            mma_bf16(acc[jj * 2], alo, bh);
            mma_bf16(acc[jj * 2], ahi, bl);
            mma_bf16(acc[jj * 2 + 1], ahi, bh + 2);
            mma_bf16(acc[jj * 2 + 1], alo, bh + 2);
            mma_bf16(acc[jj * 2 + 1], ahi, bl + 2);
        }
#pragma unroll
        for (int q = 0; q < 4; q++) raw[q] = nxt[q];
    }

    // ---- epilogue
    const int cwb = cb0 + warp_n * 64;
    float* OUT = (cwb < M) ? XL : XR;
    const int cof = (cwb < M) ? cwb : cwb - M;
    const int r0 = row0 + warp_m * 16 + (lane >> 2);
#pragma unroll
    for (int j = 0; j < 8; j++) {
        int c = cof + j * 8 + (lane & 3) * 2;
        if (r0 < n)
            *(float2*)&OUT[(size_t)r0 * M + c] = make_float2(acc[j][0], acc[j][1]);
        if (r0 + 8 < n)
            *(float2*)&OUT[(size_t)(r0 + 8) * M + c] = make_float2(acc[j][2], acc[j][3]);
    }
}

// ---------------- CSR build ----------------
__global__ void k_init_counts(int* cnt, int n) {
    int i = blockIdx.x * blockDim.x + threadIdx.x;
    if (i < n) cnt[i] = 1;
}

__global__ void k_hist(const int* __restrict__ tgt, int* cnt, int e) {
    int i = blockIdx.x * blockDim.x + threadIdx.x;
    if (i < e) atomicAdd(&cnt[tgt[i]], 1);
}

__global__ void k_scanA(const int* __restrict__ counts, int* __restrict__ lscan,
                        int* __restrict__ bsum, int n) {
    __shared__ int wsum[16];
    const int tid = threadIdx.x, lane = tid & 31, wid = tid >> 5;
    const int i = blockIdx.x * SCHUNK + tid;
    int v = (i < n) ? counts[i] : 0;
    int incl = v;
#pragma unroll
    for (int off = 1; off < 32; off <<= 1) {
        int t = __shfl_up_sync(0xffffffffu, incl, off);
        if (lane >= off) incl += t;
    }
    if (lane == 31) wsum[wid] = incl;
    __syncthreads();
    if (tid < 16) {
        int w = wsum[tid];
        int s = w;
#pragma unroll
        for (int off = 1; off < 16; off <<= 1) {
            int t = __shfl_up_sync(0xffffu, s, off);
            if (tid >= off) s += t;
        }
        wsum[tid] = s - w;
    }
    __syncthreads();
    incl += wsum[wid];
    if (i < n) lscan[i] = incl;
    if (tid == SCHUNK - 1) bsum[blockIdx.x] = incl;
}

__global__ void k_scanB(int* bsum, int nb) {
    __shared__ int wsum[4];
    const int tid = threadIdx.x, lane = tid & 31, wid = tid >> 5;
    int v = (tid < nb) ? bsum[tid] : 0;
    int incl = v;
#pragma unroll
    for (int off = 1; off < 32; off <<= 1) {
        int t = __shfl_up_sync(0xffffffffu, incl, off);
        if (lane >= off) incl += t;
    }
    if (lane == 31) wsum[wid] = incl;
    __syncthreads();
    int base = 0;
    for (int w = 0; w < wid; w++) base += wsum[w];
    if (tid < nb) bsum[tid] = base + incl - v;
}

__global__ void k_scanC(int* __restrict__ counts_cursor, const int* __restrict__ lscan,
                        const int* __restrict__ bsum, int* __restrict__ rowptr, int n) {
    int i = blockIdx.x * blockDim.x + threadIdx.x;
    if (i < n) {
        int c = counts_cursor[i];
        int incl = bsum[i / SCHUNK] + lscan[i];
        rowptr[i + 1] = incl;
        counts_cursor[i] = incl - c;
    }
    if (i == 0) rowptr[0] = 0;
}

__global__ void k_scatter(const int* __restrict__ src, const int* __restrict__ tgt,
                          int* wcur, int* col, int e, int n) {
    int i = blockIdx.x * blockDim.x + threadIdx.x;
    if (i < e) {
        int d = tgt[i];
        int p = atomicAdd(&wcur[d], 1);
        col[p] = src[i];
    } else if (i < e + n) {
        int v = i - e;
        int p = atomicAdd(&wcur[v], 1);
        col[p] = v;
    }
}

// ---------------- GATv2 aggregation (warp/node, online softmax, depth-2 prefetch) ----
template <int V>
__device__ __forceinline__ void ldrow(float* d, const float* p) {
    if (V == 4) { float4 t = *(const float4*)p; d[0]=t.x; d[1]=t.y; d[2]=t.z; d[3]=t.w; }
    else        { float2 t = *(const float2*)p; d[0]=t.x; d[1]=t.y; }
}

template <int HC, int H>
__global__ void k_gat(const float* __restrict__ XL, const float* __restrict__ XR,
                      const int* __restrict__ rowptr, const int* __restrict__ col,
                      const float* __restrict__ att, const float* __restrict__ bias,
                      float* __restrict__ Y, int n) {
    constexpr int V  = HC / 32;
    constexpr int GW = 32 / H;
    const int lane = threadIdx.x & 31;
    const int node = blockIdx.x * (blockDim.x >> 5) + (threadIdx.x >> 5);
    if (node >= n) return;

    float attv[V], bv[V], xr[V], acc[V];
#pragma unroll
    for (int v = 0; v < V; v++) {
        attv[v] = att[lane * V + v];
        bv[v]   = bias[lane * V + v];
        acc[v]  = 0.f;
    }
    ldrow<V>(xr, XR + (size_t)node * HC + lane * V);

    const int e0 = rowptr[node], e1 = rowptr[node + 1];
    float m = -3.0e38f, den = 0.f;

    auto proc = [&](const float* xl) {
        float pscore = 0.f;
#pragma unroll
        for (int v = 0; v < V; v++) {
            float t = xl[v] + xr[v];
            t = (t > 0.f) ? t : 0.2f * t;
            pscore = fmaf(attv[v], t, pscore);
        }
#pragma unroll
        for (int off = GW >> 1; off > 0; off >>= 1)
            pscore += __shfl_xor_sync(0xffffffffu, pscore, off);
        float mn   = fmaxf(m, pscore);
        float corr = __expf(m - mn);
        float w    = __expf(pscore - mn);
        den = den * corr + w;
#pragma unroll
        for (int v = 0; v < V; v++) acc[v] = fmaf(acc[v], corr, w * xl[v]);
        m = mn;
    };

    float nb0[V], nb1[V];
    ldrow<V>(nb0, XL + (size_t)__ldg(&col[e0]) * HC + lane * V);
    if (e0 + 1 < e1) ldrow<V>(nb1, XL + (size_t)__ldg(&col[e0 + 1]) * HC + lane * V);

    int e = e0;
    while (true) {
        float xl[V];
#pragma unroll
        for (int v = 0; v < V; v++) xl[v] = nb0[v];
        if (e + 2 < e1) ldrow<V>(nb0, XL + (size_t)__ldg(&col[e + 2]) * HC + lane * V);
        proc(xl);
        if (++e >= e1) break;
#pragma unroll
        for (int v = 0; v < V; v++) xl[v] = nb1[v];
        if (e + 2 < e1) ldrow<V>(nb1, XL + (size_t)__ldg(&col[e + 2]) * HC + lane * V);
        proc(xl);
        if (++e >= e1) break;
    }

    float inv = 1.f / den;
    float* yp = Y + (size_t)node * HC + lane * V;
#pragma unroll
    for (int v = 0; v < V; v++) {
        float y = fmaf(acc[v], inv, bv[v]);
        yp[v] = (y > 0.f) ? y : 0.2f * y;
    }
}

// ---------------- global mean pool ----------------
__global__ void k_zero_pool(float* out, float* cnt) {
    int i = blockIdx.x * blockDim.x + threadIdx.x;
    if (i < GG * 64) out[i] = 0.f;
    if (i < GG) cnt[i] = 0.f;
}

#define PCH 256
__global__ void k_pool2(const float* __restrict__ X, const int* __restrict__ batch,
                        float* out, float* cnt, int n) {
    const int f = threadIdx.x;
    const int chunk = blockIdx.x * blockDim.y + threadIdx.y;
    const int n0 = chunk * PCH;
    if (n0 >= n) return;
    const int n1 = min(n, n0 + PCH);
    int curg = __ldg(&batch[n0]);
    float acc = 0.f, c = 0.f;
    for (int node = n0; node < n1; node++) {
        int g = __ldg(&batch[node]);
        if (g != curg) {
            atomicAdd(&out[curg * 64 + f], acc);
            if (f == 0) atomicAdd(&cnt[curg], c);
            acc = 0.f; c = 0.f; curg = g;
        }
        acc += X[(size_t)node * 64 + f];
        c += 1.f;
    }
    atomicAdd(&out[curg * 64 + f], acc);
    if (f == 0) atomicAdd(&cnt[curg], c);
}

__global__ void k_fin(float* out, const float* __restrict__ cnt) {
    int i = blockIdx.x * blockDim.x + threadIdx.x;
    if (i < GG * 64) out[i] /= fmaxf(cnt[i >> 6], 1.f);
}

// ---------------- launch ----------------
extern "C" void kernel_launch(void* const* d_in, const int* in_sizes, int n_in,
                              void* d_out, int out_size) {
    const float* x     = (const float*)d_in[0];
    const int*   ei    = (const int*)d_in[1];
    const int*   batch = (const int*)d_in[2];
    const float* Wl0 = (const float*)d_in[3];
    const float* Wr0 = (const float*)d_in[4];
    const float* at0 = (const float*)d_in[5];
    const float* b0  = (const float*)d_in[6];
    const float* Wl1 = (const float*)d_in[7];
    const float* Wr1 = (const float*)d_in[8];
    const float* at1 = (const float*)d_in[9];
    const float* b1  = (const float*)d_in[10];
    const float* Wl2 = (const float*)d_in[11];
    const float* Wr2 = (const float*)d_in[12];
    const float* at2 = (const float*)d_in[13];
    const float* b2  = (const float*)d_in[14];
    float* out = (float*)d_out;

    const int n = in_sizes[2];
    const int e = in_sizes[1] / 2;
    const int* src = ei;
    const int* tgt = ei + e;

    float *pXL, *pXR, *pBA, *pBB, *pcnt;
    int *prow, *ptmp, *pcol, *plscan, *pbsum;
    u16 *pBhi, *pBlo;
    cudaGetSymbolAddress((void**)&pXL, g_XL);
    cudaGetSymbolAddress((void**)&pXR, g_XR);
    cudaGetSymbolAddress((void**)&pBA, g_BA);
    cudaGetSymbolAddress((void**)&pBB, g_BB);
    cudaGetSymbolAddress((void**)&prow, g_rowptr);
    cudaGetSymbolAddress((void**)&ptmp, g_tmp);
    cudaGetSymbolAddress((void**)&pcol, g_col);
    cudaGetSymbolAddress((void**)&plscan, g_lscan);
    cudaGetSymbolAddress((void**)&pbsum, g_bsum);
    cudaGetSymbolAddress((void**)&pcnt, g_cnt);
    cudaGetSymbolAddress((void**)&pBhi, g_Bhi);
    cudaGetSymbolAddress((void**)&pBlo, g_Blo);

    cudaFuncSetAttribute(k_gemm_hmma, cudaFuncAttributeMaxDynamicSharedMemorySize, GSMEM);

    const int gx      = (n + 63) / 64;   // 782
    const int ablocks = (n + 7) / 8;
    const int nsb     = (n + SCHUNK - 1) / SCHUNK;

    // layer-0 weight prep + CSR counts; GEMM positioned 4th for ncu capture
    k_prep<<<128, 256>>>(Wl0, Wr0, pBhi, pBlo, 128, 256);
    k_init_counts<<<(n + 255) / 256, 256>>>(ptmp, n);
    k_hist<<<(e + 255) / 256, 256>>>(tgt, ptmp, e);
    k_gemm_hmma<<<dim3(gx, 2), 256, GSMEM>>>(x, pBhi, pBlo, pXL, pXR, n, 128);

    k_scanA<<<nsb, SCHUNK>>>(ptmp, plscan, pbsum, n);
    k_scanB<<<1, 128>>>(pbsum, nsb);
    k_scanC<<<(n + 255) / 256, 256>>>(ptmp, plscan, pbsum, prow, n);
    k_scatter<<<(e + n + 255) / 256, 256>>>(src, tgt, ptmp, pcol, e, n);

    // layer 0 aggregate
    k_gat<128, 4><<<ablocks, 256>>>(pXL, pXR, prow, pcol, at0, b0, pBA, n);

    // layer 1
    k_prep<<<128, 256>>>(Wl1, Wr1, pBhi, pBlo, 128, 256);
    k_gemm_hmma<<<dim3(gx, 2), 256, GSMEM>>>(pBA, pBhi, pBlo, pXL, pXR, n, 128);
    k_gat<128, 4><<<ablocks, 256>>>(pXL, pXR, prow, pcol, at1, b1, pBB, n);

    // layer 2 (1 head x 64): image 128 rows (Wl|Wr), M=64
    k_prep<<<64, 256>>>(Wl2, Wr2, pBhi, pBlo, 64, 128);
    k_gemm_hmma<<<dim3(gx, 1), 256, GSMEM>>>(pBB, pBhi, pBlo, pXL, pXR, n, 64);
    k_gat<64, 1><<<ablocks, 256>>>(pXL, pXR, prow, pcol, at2, b2, pBA, n);

    // global mean pool
    k_zero_pool<<<(GG * 64 + 255) / 256, 256>>>(out, pcnt);
    {
        dim3 blk(64, 4);
        int pblocks = (n + PCH * 4 - 1) / (PCH * 4);
        k_pool2<<<pblocks, blk>>>(pBA, batch, out, pcnt, n);
    }
    k_fin<<<(GG * 64 + 255) / 256, 256>>>(out, pcnt);
}